// round 14
// baseline (speedup 1.0000x reference)
#include <cuda_runtime.h>
#include <cuda_fp16.h>
#include <cstdint>

#define B_SZ  8192
#define D_SZ  256
#define H_SZ  8192
#define K_TOP 32
#define KE    768             // 3 limb-chunks * 256 (fp16 2-limb, 3 cross terms)
#define SCAP_G 2048           // per-row survivor list capacity
#define STAGE_CAP 24          // per-CTA per-row staging capacity
#define T_VAL  2.0f

// ---------------- scratch (static device globals) ----------------
__device__ float g_tv[B_SZ * K_TOP];
__device__ int   g_ti[B_SZ * K_TOP];
__device__ __half g_A[(size_t)B_SZ * KE];                 // 12.6 MB
__device__ __half g_B[(size_t)H_SZ * KE];                 // 12.6 MB
__device__ int   g_scnt[B_SZ];                            // survivor counts
__device__ uint2 g_sl[(size_t)B_SZ * SCAP_G];             // survivor lists (bits, h)

// ---------------- helpers ----------------
__device__ __forceinline__ uint32_t smem_u32(const void* p) {
    uint32_t a;
    asm("{ .reg .u64 t; cvta.to.shared.u64 t, %1; cvt.u32.u64 %0, t; }" : "=r"(a) : "l"(p));
    return a;
}
__device__ __forceinline__ void cp_async16(uint32_t dst, const void* src) {
    asm volatile("cp.async.cg.shared.global [%0], [%1], 16;" :: "r"(dst), "l"(src));
}
#define CP_COMMIT() asm volatile("cp.async.commit_group;" ::: "memory")
#define CP_WAIT(n)  asm volatile("cp.async.wait_group %0;" :: "n"(n) : "memory")

__device__ __forceinline__ void ldsm4(uint32_t& r0, uint32_t& r1, uint32_t& r2, uint32_t& r3, uint32_t addr) {
    asm volatile("ldmatrix.sync.aligned.m8n8.x4.shared.b16 {%0,%1,%2,%3}, [%4];"
                 : "=r"(r0), "=r"(r1), "=r"(r2), "=r"(r3) : "r"(addr));
}
__device__ __forceinline__ void mma16816(float* d, const uint32_t* a, const uint32_t* b) {
    asm volatile("mma.sync.aligned.m16n8k16.row.col.f32.f16.f16.f32 "
                 "{%0,%1,%2,%3}, {%4,%5,%6,%7}, {%8,%9}, {%0,%1,%2,%3};"
                 : "+f"(d[0]), "+f"(d[1]), "+f"(d[2]), "+f"(d[3])
                 : "r"(a[0]), "r"(a[1]), "r"(a[2]), "r"(a[3]), "r"(b[0]), "r"(b[1]));
}

// ---------------------------------------------------------------------------
__global__ void zero_cnt_kernel() {
    g_scnt[blockIdx.x * blockDim.x + threadIdx.x] = 0;
}

// ---------------------------------------------------------------------------
// Split kernels: 2-limb fp16 decomposition, interleaved along K'.
// A' = [a0 | a0 | a1],  B' = [b0 | b1 | b0]  -> terms a0b0 + a0b1 + a1b0.
// ---------------------------------------------------------------------------
__device__ __forceinline__ uint32_t packh2(__half lo, __half hi) {
    __half2 h = __halves2half2(lo, hi);
    return *reinterpret_cast<uint32_t*>(&h);
}

__global__ void split_x_kernel(const float* __restrict__ x, const float* __restrict__ b_dec) {
    int i = blockIdx.x * blockDim.x + threadIdx.x;     // float4 index
    int m = i >> 6;
    int kq = (i & 63) * 4;
    float4 xv = ((const float4*)x)[i];
    float4 bv = ((const float4*)b_dec)[i & 63];
    float v[4] = {xv.x - bv.x, xv.y - bv.y, xv.z - bv.z, xv.w - bv.w};
    __half h0[4], h1[4];
#pragma unroll
    for (int j = 0; j < 4; j++) {
        h0[j] = __float2half_rn(v[j]);
        h1[j] = __float2half_rn(v[j] - __half2float(h0[j]));
    }
    uint2 p0 = {packh2(h0[0], h0[1]), packh2(h0[2], h0[3])};
    uint2 p1 = {packh2(h1[0], h1[1]), packh2(h1[2], h1[3])};
    __half* row = g_A + (size_t)m * KE + kq;
    *(uint2*)(row + 0 * 256) = p0;       // a0
    *(uint2*)(row + 1 * 256) = p0;       // a0
    *(uint2*)(row + 2 * 256) = p1;       // a1
}

__global__ void split_w_kernel(const float* __restrict__ w) {
    int i = blockIdx.x * blockDim.x + threadIdx.x;
    int n = i >> 6;
    int kq = (i & 63) * 4;
    float4 wv = ((const float4*)w)[i];
    float v[4] = {wv.x, wv.y, wv.z, wv.w};
    __half h0[4], h1[4];
#pragma unroll
    for (int j = 0; j < 4; j++) {
        h0[j] = __float2half_rn(v[j]);
        h1[j] = __float2half_rn(v[j] - __half2float(h0[j]));
    }
    uint2 p0 = {packh2(h0[0], h0[1]), packh2(h0[2], h0[3])};
    uint2 p1 = {packh2(h1[0], h1[1]), packh2(h1[2], h1[3])};
    __half* row = g_B + (size_t)n * KE + kq;
    *(uint2*)(row + 0 * 256) = p0;       // b0
    *(uint2*)(row + 1 * 256) = p1;       // b1
    *(uint2*)(row + 2 * 256) = p0;       // b0
}

// ---------------------------------------------------------------------------
// Encoder GEMM: BM=128 x BN=128, GBK=64, 3 stages, 256 threads, 2 CTAs/SM.
// No pre_acts store: epilogue only stages survivors (v > 2.0) per-row.
// ---------------------------------------------------------------------------
#define BM 128
#define BN 128
#define GBK 64
#define STAGES 3
#define KT (KE / GBK)                       // 12
#define A_ST_BYTES (BM * GBK * 2)           // 16384
#define B_ST_BYTES (BN * GBK * 2)           // 16384
#define ST_BYTES   (A_ST_BYTES + B_ST_BYTES)
#define SMEM_GEMM  (STAGES * ST_BYTES)      // 98304

// SW128: 128-byte rows, 8x16B chunks, chunk XOR row&7
__device__ __forceinline__ uint32_t sw_off(int row, int c) {
    return (uint32_t)(row * 128 + ((c ^ (row & 7)) << 4));
}

__device__ __forceinline__ void stage_load(uint32_t sbase, int st, int kt, int tid,
                                           const __half* gA, const __half* gB) {
    uint32_t sa = sbase + st * ST_BYTES;
    uint32_t sb = sa + A_ST_BYTES;
    int k0 = kt * GBK;
#pragma unroll
    for (int i = 0; i < 4; i++) {
        int idx = tid + i * 256;            // 0..1023 chunks (128 rows x 8)
        int row = idx >> 3, c = idx & 7;
        cp_async16(sa + sw_off(row, c), gA + (size_t)row * KE + k0 + c * 8);
    }
#pragma unroll
    for (int i = 0; i < 4; i++) {
        int idx = tid + i * 256;
        int row = idx >> 3, c = idx & 7;
        cp_async16(sb + sw_off(row, c), gB + (size_t)row * KE + k0 + c * 8);
    }
}

__global__ __launch_bounds__(256, 2)
void enc_mma_kernel(const float* __restrict__ b_enc) {
    extern __shared__ char smem[];
    __shared__ float s_be[BN];
    __shared__ int s_rcnt[BM];

    const uint32_t sbase = smem_u32(smem);
    const int tid = threadIdx.x;
    const int wid = tid >> 5, lid = tid & 31;
    const int n0 = blockIdx.x * BN;
    const int m0 = blockIdx.y * BM;
    const int wm = (wid & 3) * 32;           // 4 warps over M
    const int wn = (wid >> 2) * 64;          // 2 warps over N

    if (tid < BN) s_be[tid] = b_enc[n0 + tid];

    const __half* gA = g_A + (size_t)m0 * KE;
    const __half* gB = g_B + (size_t)n0 * KE;

    float d[2][8][4];
#pragma unroll
    for (int mt = 0; mt < 2; mt++)
#pragma unroll
        for (int nt = 0; nt < 8; nt++)
#pragma unroll
            for (int j = 0; j < 4; j++) d[mt][nt][j] = 0.0f;

#pragma unroll
    for (int s = 0; s < STAGES - 1; s++) { stage_load(sbase, s, s, tid, gA, gB); CP_COMMIT(); }

    const int g  = lid >> 3;
    const int lr = lid & 7;

#pragma unroll 1
    for (int kt = 0; kt < KT; kt++) {
        CP_WAIT(1);
        __syncthreads();
        const int st3 = kt % STAGES;
        const uint32_t sa = sbase + st3 * ST_BYTES;
        const uint32_t sb = sa + A_ST_BYTES;

        if (kt + STAGES - 1 < KT)
            stage_load(sbase, (kt + STAGES - 1) % STAGES, kt + STAGES - 1, tid, gA, gB);
        CP_COMMIT();

#pragma unroll
        for (int ks = 0; ks < 4; ks++) {
            uint32_t a[2][4], b[4][4];
#pragma unroll
            for (int mt = 0; mt < 2; mt++) {
                int row = wm + mt * 16 + (g & 1) * 8 + lr;
                int c   = ks * 2 + (g >> 1);
                ldsm4(a[mt][0], a[mt][1], a[mt][2], a[mt][3], sa + sw_off(row, c));
            }
#pragma unroll
            for (int np = 0; np < 4; np++) {
                int row = wn + (np * 2 + (g >> 1)) * 8 + lr;
                int c   = ks * 2 + (g & 1);
                ldsm4(b[np][0], b[np][1], b[np][2], b[np][3], sb + sw_off(row, c));
            }
#pragma unroll
            for (int mt = 0; mt < 2; mt++)
#pragma unroll
                for (int nt = 0; nt < 8; nt++)
                    mma16816(d[mt][nt], a[mt], &b[nt >> 1][(nt & 1) * 2]);
        }
        __syncthreads();
    }

    // ---- epilogue: bias + relu + smem-staged survivor emit (no g_pre) ----
    uint2* s_stage = (uint2*)smem;                         // [BM][STAGE_CAP]
    if (tid < BM) s_rcnt[tid] = 0;
    __syncthreads();

#pragma unroll
    for (int mt = 0; mt < 2; mt++) {
        int lrow0 = wm + mt * 16 + (lid >> 2);             // local row
#pragma unroll
        for (int nt = 0; nt < 8; nt++) {
            int coll = wn + nt * 8 + (lid & 3) * 2;
            float be0 = s_be[coll], be1 = s_be[coll + 1];
            float v00 = d[mt][nt][0] + be0;
            float v01 = d[mt][nt][1] + be1;
            float v10 = d[mt][nt][2] + be0;
            float v11 = d[mt][nt][3] + be1;
            if (v00 > T_VAL) {
                int q = atomicAdd(&s_rcnt[lrow0], 1);
                if (q < STAGE_CAP) s_stage[lrow0 * STAGE_CAP + q] = make_uint2(__float_as_uint(v00), (unsigned)(n0 + coll));
            }
            if (v01 > T_VAL) {
                int q = atomicAdd(&s_rcnt[lrow0], 1);
                if (q < STAGE_CAP) s_stage[lrow0 * STAGE_CAP + q] = make_uint2(__float_as_uint(v01), (unsigned)(n0 + coll + 1));
            }
            if (v10 > T_VAL) {
                int q = atomicAdd(&s_rcnt[lrow0 + 8], 1);
                if (q < STAGE_CAP) s_stage[(lrow0 + 8) * STAGE_CAP + q] = make_uint2(__float_as_uint(v10), (unsigned)(n0 + coll));
            }
            if (v11 > T_VAL) {
                int q = atomicAdd(&s_rcnt[lrow0 + 8], 1);
                if (q < STAGE_CAP) s_stage[(lrow0 + 8) * STAGE_CAP + q] = make_uint2(__float_as_uint(v11), (unsigned)(n0 + coll + 1));
            }
        }
    }
    __syncthreads();

    // flush: one global atomic per row; poison on overflow -> exact fallback
    if (tid < BM) {
        int cnt = s_rcnt[tid];
        int row = m0 + tid;
        if (cnt <= STAGE_CAP) {
            if (cnt > 0) {
                int base = atomicAdd(&g_scnt[row], cnt);
                if (base + cnt <= SCAP_G) {
                    uint2* dst = g_sl + (size_t)row * SCAP_G + base;
                    for (int q = 0; q < cnt; q++) dst[q] = s_stage[tid * STAGE_CAP + q];
                }
            }
        } else {
            atomicAdd(&g_scnt[row], 1 << 20);   // poison -> fallback
        }
    }
}

// ---------------------------------------------------------------------------
// Top-32 v6: per-row survivor list, exact select. Fallback (rare/never):
// recompute the row in fp32 from x/W_enc/b_enc/b_dec, select from registers.
// ---------------------------------------------------------------------------
#define HBINS 2048
#define CAP   2048

__device__ __forceinline__ void suffix2048(const int* s_hist, int* s_warp, int tid,
                                           int& local, int& suf_incl, int& total) {
    local = 0;
#pragma unroll
    for (int b = 0; b < 8; b++) local += s_hist[tid * 8 + b];
    int v = local;
    const int lane = tid & 31, w = tid >> 5;
#pragma unroll
    for (int off = 1; off < 32; off <<= 1) {
        int t = __shfl_down_sync(0xFFFFFFFFu, v, off);
        if (lane + off < 32) v += t;
    }
    if (lane == 0) s_warp[w] = v;
    __syncthreads();
    int add = 0;
#pragma unroll
    for (int ww = 0; ww < 8; ww++) if (ww > w) add += s_warp[ww];
    suf_incl = v + add;
    total = 0;
#pragma unroll
    for (int ww = 0; ww < 8; ww++) total += s_warp[ww];
}

__global__ __launch_bounds__(256)
void topk_kernel(const float* __restrict__ x, const float* __restrict__ Wenc,
                 const float* __restrict__ benc, const float* __restrict__ bdec) {
    __shared__ int s_hist[HBINS];
    __shared__ int s_warp[8];
    __shared__ int s_scan[128];
    __shared__ unsigned s_su[CAP];
    __shared__ int s_si[CAP];
    __shared__ unsigned s_cu[CAP];
    __shared__ int s_ci[CAP];
    __shared__ float s_x[D_SZ];
    __shared__ int s_B1, s_above, s_cnt, s_ccnt, s_sel;

    const int tid = threadIdx.x;
    const int r = blockIdx.x;

    if (tid < K_TOP) { g_tv[r * K_TOP + tid] = 0.0f; g_ti[r * K_TOP + tid] = 0; }
#pragma unroll
    for (int i = tid; i < HBINS; i += 256) s_hist[i] = 0;
    if (tid == 0) { s_B1 = -1; s_above = 0; s_cnt = 0; s_ccnt = 0; }
    __syncthreads();

    const int scnt_raw = g_scnt[r];

    if (scnt_raw >= K_TOP && scnt_raw <= SCAP_G) {
        const int scnt = scnt_raw;
        const uint2* sl = g_sl + (size_t)r * SCAP_G;
        for (int i = tid; i < scnt; i += 256) {
            uint2 e = sl[i];
            s_su[i] = e.x; s_si[i] = (int)e.y;
        }
        __syncthreads();

        for (int i = tid; i < scnt; i += 256) atomicAdd(&s_hist[s_su[i] >> 21], 1);
        __syncthreads();

        int local, suf, total;
        suffix2048(s_hist, s_warp, tid, local, suf, total);
        {
            int run = suf - local;
#pragma unroll
            for (int b = 7; b >= 0; b--) {
                int h = s_hist[tid * 8 + b];
                if (run < K_TOP && run + h >= K_TOP) { s_B1 = tid * 8 + b; s_above = run; }
                run += h;
            }
        }
        __syncthreads();
        const int B1 = s_B1;

        for (int i = tid; i < scnt; i += 256) {
            unsigned uu = s_su[i];
            int key = (int)(uu >> 21);
            if (key > B1) {
                int p = atomicAdd(&s_cnt, 1);
                g_tv[r * K_TOP + p] = __uint_as_float(uu);
                g_ti[r * K_TOP + p] = s_si[i];
            } else if (key == B1) {
                int p = atomicAdd(&s_ccnt, 1);
                s_cu[p] = uu & 0x1FFFFFu; s_ci[p] = s_si[i];
            }
        }
        __syncthreads();

        int krem = K_TOP - s_above;
        int ccnt = s_ccnt;

        if (ccnt <= krem) {
            for (int i = tid; i < ccnt; i += 256) {
                int p = atomicAdd(&s_cnt, 1);
                g_tv[r * K_TOP + p] = __uint_as_float(((unsigned)B1 << 21) | s_cu[i]);
                g_ti[r * K_TOP + p] = s_ci[i];
            }
            return;
        }

        unsigned prefix21 = 0;
#pragma unroll 1
        for (int shift = 14; shift >= 0; shift -= 7) {
            if (tid < 128) s_hist[tid] = 0;
            if (tid == 0) s_sel = 0;
            __syncthreads();
            unsigned pmask = (shift == 14) ? 0u : ((0x1FFFFFu << (shift + 7)) & 0x1FFFFFu);
            for (int i = tid; i < ccnt; i += 256) {
                unsigned cu = s_cu[i];
                if ((cu & pmask) == prefix21) atomicAdd(&s_hist[(cu >> shift) & 127], 1);
            }
            __syncthreads();
            if (tid < 128) s_scan[tid] = s_hist[tid];
            __syncthreads();
#pragma unroll 1
            for (int off = 1; off < 128; off <<= 1) {
                int add = (tid < 128 && tid + off < 128) ? s_scan[tid + off] : 0;
                __syncthreads();
                if (tid < 128) s_scan[tid] += add;
                __syncthreads();
            }
            if (tid < 128) {
                int nxt = (tid < 127) ? s_scan[tid + 1] : 0;
                if (s_scan[tid] >= krem && nxt < krem) s_sel = tid;
            }
            __syncthreads();
            int dsel = s_sel;
            int above2 = (dsel < 127) ? s_scan[dsel + 1] : 0;
            krem -= above2;
            prefix21 |= ((unsigned)dsel) << shift;
            __syncthreads();
        }
        const unsigned kth_low = prefix21;
        for (int i = tid; i < ccnt; i += 256) {
            if (s_cu[i] > kth_low) {
                int p = atomicAdd(&s_cnt, 1);
                g_tv[r * K_TOP + p] = __uint_as_float(((unsigned)B1 << 21) | s_cu[i]);
                g_ti[r * K_TOP + p] = s_ci[i];
            }
        }
        __syncthreads();
        for (int i = tid; i < ccnt; i += 256) {
            if (s_cu[i] == kth_low) {
                int p = atomicAdd(&s_cnt, 1);
                if (p < K_TOP) {
                    g_tv[r * K_TOP + p] = __uint_as_float(((unsigned)B1 << 21) | s_cu[i]);
                    g_ti[r * K_TOP + p] = s_ci[i];
                }
            }
        }
        return;
    }

    // -------- fallback (rare/never): recompute row in fp32, register select --------
    s_x[tid] = x[(size_t)r * D_SZ + tid] - bdec[tid];
    __syncthreads();

    unsigned u[32];
#pragma unroll 1
    for (int j = 0; j < 32; j++) {
        int h = tid * 32 + j;
        const float4* w4 = (const float4*)(Wenc + (size_t)h * D_SZ);
        float acc = benc[h];
#pragma unroll
        for (int dq = 0; dq < 64; dq++) {
            float4 wv = w4[dq];
            acc += s_x[dq * 4 + 0] * wv.x + s_x[dq * 4 + 1] * wv.y
                 + s_x[dq * 4 + 2] * wv.z + s_x[dq * 4 + 3] * wv.w;
        }
        u[j] = __float_as_uint(fmaxf(acc, 0.0f));
    }

#pragma unroll
    for (int j = 0; j < 32; j++)
        if (u[j]) atomicAdd(&s_hist[u[j] >> 21], 1);
    __syncthreads();

    int local, suf, total;
    suffix2048(s_hist, s_warp, tid, local, suf, total);
    {
        int run = suf - local;
#pragma unroll
        for (int b = 7; b >= 0; b--) {
            int h = s_hist[tid * 8 + b];
            if (run < K_TOP && run + h >= K_TOP) { s_B1 = tid * 8 + b; s_above = run; }
            run += h;
        }
    }
    __syncthreads();

    if (total < K_TOP) {
#pragma unroll
        for (int j = 0; j < 32; j++) {
            if (u[j]) {
                int p = atomicAdd(&s_cnt, 1);
                g_tv[r * K_TOP + p] = __uint_as_float(u[j]);
                g_ti[r * K_TOP + p] = tid * 32 + j;
            }
        }
        return;
    }

    const int B1 = s_B1;
#pragma unroll
    for (int j = 0; j < 32; j++) {
        unsigned uu = u[j];
        if (!uu) continue;
        int key = (int)(uu >> 21);
        int idx = tid * 32 + j;
        if (key > B1) {
            int p = atomicAdd(&s_cnt, 1);
            g_tv[r * K_TOP + p] = __uint_as_float(uu);
            g_ti[r * K_TOP + p] = idx;
        } else if (key == B1) {
            int p = atomicAdd(&s_ccnt, 1);
            if (p < CAP) { s_cu[p] = uu & 0x1FFFFFu; s_ci[p] = idx; }
        }
    }
    __syncthreads();

    int krem = K_TOP - s_above;
    int ccnt = s_ccnt < CAP ? s_ccnt : CAP;

    if (ccnt <= krem) {
        for (int i = tid; i < ccnt; i += 256) {
            int p = atomicAdd(&s_cnt, 1);
            g_tv[r * K_TOP + p] = __uint_as_float(((unsigned)B1 << 21) | s_cu[i]);
            g_ti[r * K_TOP + p] = s_ci[i];
        }
        return;
    }

    unsigned prefix21 = 0;
#pragma unroll 1
    for (int shift = 14; shift >= 0; shift -= 7) {
        if (tid < 128) s_hist[tid] = 0;
        if (tid == 0) s_sel = 0;
        __syncthreads();
        unsigned pmask = (shift == 14) ? 0u : ((0x1FFFFFu << (shift + 7)) & 0x1FFFFFu);
        for (int i = tid; i < ccnt; i += 256) {
            unsigned cu = s_cu[i];
            if ((cu & pmask) == prefix21) atomicAdd(&s_hist[(cu >> shift) & 127], 1);
        }
        __syncthreads();
        if (tid < 128) s_scan[tid] = s_hist[tid];
        __syncthreads();
#pragma unroll 1
        for (int off = 1; off < 128; off <<= 1) {
            int add = (tid < 128 && tid + off < 128) ? s_scan[tid + off] : 0;
            __syncthreads();
            if (tid < 128) s_scan[tid] += add;
            __syncthreads();
        }
        if (tid < 128) {
            int nxt = (tid < 127) ? s_scan[tid + 1] : 0;
            if (s_scan[tid] >= krem && nxt < krem) s_sel = tid;
        }
        __syncthreads();
        int dsel = s_sel;
        int above2 = (dsel < 127) ? s_scan[dsel + 1] : 0;
        krem -= above2;
        prefix21 |= ((unsigned)dsel) << shift;
        __syncthreads();
    }
    const unsigned kth_low = prefix21;

    for (int i = tid; i < ccnt; i += 256) {
        if (s_cu[i] > kth_low) {
            int p = atomicAdd(&s_cnt, 1);
            g_tv[r * K_TOP + p] = __uint_as_float(((unsigned)B1 << 21) | s_cu[i]);
            g_ti[r * K_TOP + p] = s_ci[i];
        }
    }
    __syncthreads();
    for (int i = tid; i < ccnt; i += 256) {
        if (s_cu[i] == kth_low) {
            int p = atomicAdd(&s_cnt, 1);
            if (p < K_TOP) {
                g_tv[r * K_TOP + p] = __uint_as_float(((unsigned)B1 << 21) | s_cu[i]);
                g_ti[r * K_TOP + p] = s_ci[i];
            }
        }
    }
}

// ---------------------------------------------------------------------------
// Sparse decode (unchanged)
// ---------------------------------------------------------------------------
__global__ __launch_bounds__(256)
void decode_kernel(const float* __restrict__ Wdec,
                   const float* __restrict__ b_dec,
                   float* __restrict__ out) {
    const int r = blockIdx.x;
    const int d = threadIdx.x;
    float acc = b_dec[d];
#pragma unroll
    for (int k = 0; k < K_TOP; k++) {
        float v  = g_tv[r * K_TOP + k];
        int   ix = g_ti[r * K_TOP + k];
        acc += v * __ldg(Wdec + (size_t)ix * D_SZ + d);
    }
    out[(size_t)r * D_SZ + d] = acc;
}

// ---------------------------------------------------------------------------
extern "C" void kernel_launch(void* const* d_in, const int* in_sizes, int n_in,
                              void* d_out, int out_size) {
    const float* x    = (const float*)d_in[0];
    const float* Wenc = (const float*)d_in[1];
    const float* benc = (const float*)d_in[2];
    const float* Wdec = (const float*)d_in[3];
    const float* bdec = (const float*)d_in[4];
    float* out = (float*)d_out;

    zero_cnt_kernel<<<B_SZ / 256, 256>>>();
    split_x_kernel<<<(B_SZ * D_SZ / 4) / 256, 256>>>(x, bdec);
    split_w_kernel<<<(H_SZ * D_SZ / 4) / 256, 256>>>(Wenc);

    static bool attr_set = false;
    if (!attr_set) {
        cudaFuncSetAttribute(enc_mma_kernel, cudaFuncAttributeMaxDynamicSharedMemorySize, SMEM_GEMM);
        attr_set = true;
    }
    dim3 grid(H_SZ / BN, B_SZ / BM);
    enc_mma_kernel<<<grid, 256, SMEM_GEMM>>>(benc);

    topk_kernel<<<B_SZ, 256>>>(x, Wenc, benc, bdec);

    decode_kernel<<<B_SZ, 256>>>(Wdec, bdec, out);
}

// round 16
// speedup vs baseline: 1.3781x; 1.3781x over previous
#include <cuda_runtime.h>
#include <cuda_fp16.h>
#include <cstdint>

#define B_SZ  8192
#define D_SZ  256
#define H_SZ  8192
#define K_TOP 32
#define KE    768             // 3 limb-chunks * 256 (fp16 2-limb, 3 cross terms)
#define SCAP_G 2048           // per-row survivor list capacity
#define STAGE_CAP 24          // per-CTA per-row staging capacity
#define T_VAL  2.0f

// ---------------- scratch (static device globals) ----------------
__device__ float g_tv[B_SZ * K_TOP];
__device__ int   g_ti[B_SZ * K_TOP];
__device__ __half g_A[(size_t)B_SZ * KE];                 // 12.6 MB
__device__ __half g_B[(size_t)H_SZ * KE];                 // 12.6 MB
__device__ int   g_scnt[B_SZ];                            // survivor counts
__device__ uint2 g_sl[(size_t)B_SZ * SCAP_G];             // survivor lists (bits, h)

// ---------------- helpers ----------------
__device__ __forceinline__ uint32_t smem_u32(const void* p) {
    uint32_t a;
    asm("{ .reg .u64 t; cvta.to.shared.u64 t, %1; cvt.u32.u64 %0, t; }" : "=r"(a) : "l"(p));
    return a;
}
__device__ __forceinline__ void cp_async16(uint32_t dst, const void* src) {
    asm volatile("cp.async.cg.shared.global [%0], [%1], 16;" :: "r"(dst), "l"(src));
}
#define CP_COMMIT() asm volatile("cp.async.commit_group;" ::: "memory")
#define CP_WAIT(n)  asm volatile("cp.async.wait_group %0;" :: "n"(n) : "memory")

__device__ __forceinline__ void ldsm4(uint32_t& r0, uint32_t& r1, uint32_t& r2, uint32_t& r3, uint32_t addr) {
    asm volatile("ldmatrix.sync.aligned.m8n8.x4.shared.b16 {%0,%1,%2,%3}, [%4];"
                 : "=r"(r0), "=r"(r1), "=r"(r2), "=r"(r3) : "r"(addr));
}
__device__ __forceinline__ void mma16816(float* d, const uint32_t* a, const uint32_t* b) {
    asm volatile("mma.sync.aligned.m16n8k16.row.col.f32.f16.f16.f32 "
                 "{%0,%1,%2,%3}, {%4,%5,%6,%7}, {%8,%9}, {%0,%1,%2,%3};"
                 : "+f"(d[0]), "+f"(d[1]), "+f"(d[2]), "+f"(d[3])
                 : "r"(a[0]), "r"(a[1]), "r"(a[2]), "r"(a[3]), "r"(b[0]), "r"(b[1]));
}

// ---------------------------------------------------------------------------
__global__ void zero_cnt_kernel() {
    g_scnt[blockIdx.x * blockDim.x + threadIdx.x] = 0;
}

// ---------------------------------------------------------------------------
// Split kernels: 2-limb fp16 decomposition, interleaved along K'.
// A' = [a0 | a0 | a1],  B' = [b0 | b1 | b0]  -> terms a0b0 + a0b1 + a1b0.
// ---------------------------------------------------------------------------
__device__ __forceinline__ uint32_t packh2(__half lo, __half hi) {
    __half2 h = __halves2half2(lo, hi);
    return *reinterpret_cast<uint32_t*>(&h);
}

__global__ void split_x_kernel(const float* __restrict__ x, const float* __restrict__ b_dec) {
    int i = blockIdx.x * blockDim.x + threadIdx.x;     // float4 index
    int m = i >> 6;
    int kq = (i & 63) * 4;
    float4 xv = ((const float4*)x)[i];
    float4 bv = ((const float4*)b_dec)[i & 63];
    float v[4] = {xv.x - bv.x, xv.y - bv.y, xv.z - bv.z, xv.w - bv.w};
    __half h0[4], h1[4];
#pragma unroll
    for (int j = 0; j < 4; j++) {
        h0[j] = __float2half_rn(v[j]);
        h1[j] = __float2half_rn(v[j] - __half2float(h0[j]));
    }
    uint2 p0 = {packh2(h0[0], h0[1]), packh2(h0[2], h0[3])};
    uint2 p1 = {packh2(h1[0], h1[1]), packh2(h1[2], h1[3])};
    __half* row = g_A + (size_t)m * KE + kq;
    *(uint2*)(row + 0 * 256) = p0;       // a0
    *(uint2*)(row + 1 * 256) = p0;       // a0
    *(uint2*)(row + 2 * 256) = p1;       // a1
}

__global__ void split_w_kernel(const float* __restrict__ w) {
    int i = blockIdx.x * blockDim.x + threadIdx.x;
    int n = i >> 6;
    int kq = (i & 63) * 4;
    float4 wv = ((const float4*)w)[i];
    float v[4] = {wv.x, wv.y, wv.z, wv.w};
    __half h0[4], h1[4];
#pragma unroll
    for (int j = 0; j < 4; j++) {
        h0[j] = __float2half_rn(v[j]);
        h1[j] = __float2half_rn(v[j] - __half2float(h0[j]));
    }
    uint2 p0 = {packh2(h0[0], h0[1]), packh2(h0[2], h0[3])};
    uint2 p1 = {packh2(h1[0], h1[1]), packh2(h1[2], h1[3])};
    __half* row = g_B + (size_t)n * KE + kq;
    *(uint2*)(row + 0 * 256) = p0;       // b0
    *(uint2*)(row + 1 * 256) = p1;       // b1
    *(uint2*)(row + 2 * 256) = p0;       // b0
}

// ---------------------------------------------------------------------------
// Encoder GEMM: BM=128 x BN=128, GBK=64, 3 stages, 256 threads, 2 CTAs/SM.
// No pre_acts store: epilogue only stages survivors (v > 2.0) per-row. (R14)
// ---------------------------------------------------------------------------
#define BM 128
#define BN 128
#define GBK 64
#define STAGES 3
#define KT (KE / GBK)                       // 12
#define A_ST_BYTES (BM * GBK * 2)           // 16384
#define B_ST_BYTES (BN * GBK * 2)           // 16384
#define ST_BYTES   (A_ST_BYTES + B_ST_BYTES)
#define SMEM_GEMM  (STAGES * ST_BYTES)      // 98304

// SW128: 128-byte rows, 8x16B chunks, chunk XOR row&7
__device__ __forceinline__ uint32_t sw_off(int row, int c) {
    return (uint32_t)(row * 128 + ((c ^ (row & 7)) << 4));
}

__device__ __forceinline__ void stage_load(uint32_t sbase, int st, int kt, int tid,
                                           const __half* gA, const __half* gB) {
    uint32_t sa = sbase + st * ST_BYTES;
    uint32_t sb = sa + A_ST_BYTES;
    int k0 = kt * GBK;
#pragma unroll
    for (int i = 0; i < 4; i++) {
        int idx = tid + i * 256;            // 0..1023 chunks (128 rows x 8)
        int row = idx >> 3, c = idx & 7;
        cp_async16(sa + sw_off(row, c), gA + (size_t)row * KE + k0 + c * 8);
    }
#pragma unroll
    for (int i = 0; i < 4; i++) {
        int idx = tid + i * 256;
        int row = idx >> 3, c = idx & 7;
        cp_async16(sb + sw_off(row, c), gB + (size_t)row * KE + k0 + c * 8);
    }
}

__global__ __launch_bounds__(256, 2)
void enc_mma_kernel(const float* __restrict__ b_enc) {
    extern __shared__ char smem[];
    __shared__ float s_be[BN];
    __shared__ int s_rcnt[BM];

    const uint32_t sbase = smem_u32(smem);
    const int tid = threadIdx.x;
    const int wid = tid >> 5, lid = tid & 31;
    const int n0 = blockIdx.x * BN;
    const int m0 = blockIdx.y * BM;
    const int wm = (wid & 3) * 32;           // 4 warps over M
    const int wn = (wid >> 2) * 64;          // 2 warps over N

    if (tid < BN) s_be[tid] = b_enc[n0 + tid];

    const __half* gA = g_A + (size_t)m0 * KE;
    const __half* gB = g_B + (size_t)n0 * KE;

    float d[2][8][4];
#pragma unroll
    for (int mt = 0; mt < 2; mt++)
#pragma unroll
        for (int nt = 0; nt < 8; nt++)
#pragma unroll
            for (int j = 0; j < 4; j++) d[mt][nt][j] = 0.0f;

#pragma unroll
    for (int s = 0; s < STAGES - 1; s++) { stage_load(sbase, s, s, tid, gA, gB); CP_COMMIT(); }

    const int g  = lid >> 3;
    const int lr = lid & 7;

#pragma unroll 1
    for (int kt = 0; kt < KT; kt++) {
        CP_WAIT(1);
        __syncthreads();
        const int st3 = kt % STAGES;
        const uint32_t sa = sbase + st3 * ST_BYTES;
        const uint32_t sb = sa + A_ST_BYTES;

        if (kt + STAGES - 1 < KT)
            stage_load(sbase, (kt + STAGES - 1) % STAGES, kt + STAGES - 1, tid, gA, gB);
        CP_COMMIT();

#pragma unroll
        for (int ks = 0; ks < 4; ks++) {
            uint32_t a[2][4], b[4][4];
#pragma unroll
            for (int mt = 0; mt < 2; mt++) {
                int row = wm + mt * 16 + (g & 1) * 8 + lr;
                int c   = ks * 2 + (g >> 1);
                ldsm4(a[mt][0], a[mt][1], a[mt][2], a[mt][3], sa + sw_off(row, c));
            }
#pragma unroll
            for (int np = 0; np < 4; np++) {
                int row = wn + (np * 2 + (g >> 1)) * 8 + lr;
                int c   = ks * 2 + (g & 1);
                ldsm4(b[np][0], b[np][1], b[np][2], b[np][3], sb + sw_off(row, c));
            }
#pragma unroll
            for (int mt = 0; mt < 2; mt++)
#pragma unroll
                for (int nt = 0; nt < 8; nt++)
                    mma16816(d[mt][nt], a[mt], &b[nt >> 1][(nt & 1) * 2]);
        }
        __syncthreads();
    }

    // ---- epilogue: bias + relu + smem-staged survivor emit (no g_pre) ----
    uint2* s_stage = (uint2*)smem;                         // [BM][STAGE_CAP]
    if (tid < BM) s_rcnt[tid] = 0;
    __syncthreads();

#pragma unroll
    for (int mt = 0; mt < 2; mt++) {
        int lrow0 = wm + mt * 16 + (lid >> 2);             // local row
#pragma unroll
        for (int nt = 0; nt < 8; nt++) {
            int coll = wn + nt * 8 + (lid & 3) * 2;
            float be0 = s_be[coll], be1 = s_be[coll + 1];
            float v00 = d[mt][nt][0] + be0;
            float v01 = d[mt][nt][1] + be1;
            float v10 = d[mt][nt][2] + be0;
            float v11 = d[mt][nt][3] + be1;
            if (v00 > T_VAL) {
                int q = atomicAdd(&s_rcnt[lrow0], 1);
                if (q < STAGE_CAP) s_stage[lrow0 * STAGE_CAP + q] = make_uint2(__float_as_uint(v00), (unsigned)(n0 + coll));
            }
            if (v01 > T_VAL) {
                int q = atomicAdd(&s_rcnt[lrow0], 1);
                if (q < STAGE_CAP) s_stage[lrow0 * STAGE_CAP + q] = make_uint2(__float_as_uint(v01), (unsigned)(n0 + coll + 1));
            }
            if (v10 > T_VAL) {
                int q = atomicAdd(&s_rcnt[lrow0 + 8], 1);
                if (q < STAGE_CAP) s_stage[(lrow0 + 8) * STAGE_CAP + q] = make_uint2(__float_as_uint(v10), (unsigned)(n0 + coll));
            }
            if (v11 > T_VAL) {
                int q = atomicAdd(&s_rcnt[lrow0 + 8], 1);
                if (q < STAGE_CAP) s_stage[(lrow0 + 8) * STAGE_CAP + q] = make_uint2(__float_as_uint(v11), (unsigned)(n0 + coll + 1));
            }
        }
    }
    __syncthreads();

    // flush: one global atomic per row; poison on overflow -> exact fallback
    if (tid < BM) {
        int cnt = s_rcnt[tid];
        int row = m0 + tid;
        if (cnt <= STAGE_CAP) {
            if (cnt > 0) {
                int base = atomicAdd(&g_scnt[row], cnt);
                if (base + cnt <= SCAP_G) {
                    uint2* dst = g_sl + (size_t)row * SCAP_G + base;
                    for (int q = 0; q < cnt; q++) dst[q] = s_stage[tid * STAGE_CAP + q];
                }
            }
        } else {
            atomicAdd(&g_scnt[row], 1 << 20);   // poison -> fallback
        }
    }
}

// ---------------------------------------------------------------------------
// Top-32 fast kernel: survivor-list exact select ONLY (low regs, high occ).
// Rows with invalid counts just get zero-init; fallback kernel handles them.
// ---------------------------------------------------------------------------
#define HBINS 2048
#define CAP   2048

__device__ __forceinline__ void suffix2048(const int* s_hist, int* s_warp, int tid,
                                           int& local, int& suf_incl, int& total) {
    local = 0;
#pragma unroll
    for (int b = 0; b < 8; b++) local += s_hist[tid * 8 + b];
    int v = local;
    const int lane = tid & 31, w = tid >> 5;
#pragma unroll
    for (int off = 1; off < 32; off <<= 1) {
        int t = __shfl_down_sync(0xFFFFFFFFu, v, off);
        if (lane + off < 32) v += t;
    }
    if (lane == 0) s_warp[w] = v;
    __syncthreads();
    int add = 0;
#pragma unroll
    for (int ww = 0; ww < 8; ww++) if (ww > w) add += s_warp[ww];
    suf_incl = v + add;
    total = 0;
#pragma unroll
    for (int ww = 0; ww < 8; ww++) total += s_warp[ww];
}

__global__ __launch_bounds__(256)
void topk_fast_kernel() {
    __shared__ int s_hist[HBINS];
    __shared__ int s_warp[8];
    __shared__ int s_scan[128];
    __shared__ unsigned s_su[CAP];
    __shared__ int s_si[CAP];
    __shared__ unsigned s_cu[CAP];
    __shared__ int s_ci[CAP];
    __shared__ int s_B1, s_above, s_cnt, s_ccnt, s_sel;

    const int tid = threadIdx.x;
    const int r = blockIdx.x;

    if (tid < K_TOP) { g_tv[r * K_TOP + tid] = 0.0f; g_ti[r * K_TOP + tid] = 0; }

    const int scnt_raw = g_scnt[r];
    if (scnt_raw < K_TOP || scnt_raw > SCAP_G) return;   // fallback kernel owns this row

#pragma unroll
    for (int i = tid; i < HBINS; i += 256) s_hist[i] = 0;
    if (tid == 0) { s_B1 = -1; s_above = 0; s_cnt = 0; s_ccnt = 0; }
    __syncthreads();

    const int scnt = scnt_raw;
    const uint2* sl = g_sl + (size_t)r * SCAP_G;
    for (int i = tid; i < scnt; i += 256) {
        uint2 e = sl[i];
        s_su[i] = e.x; s_si[i] = (int)e.y;
    }
    __syncthreads();

    for (int i = tid; i < scnt; i += 256) atomicAdd(&s_hist[s_su[i] >> 21], 1);
    __syncthreads();

    int local, suf, total;
    suffix2048(s_hist, s_warp, tid, local, suf, total);
    {
        int run = suf - local;
#pragma unroll
        for (int b = 7; b >= 0; b--) {
            int h = s_hist[tid * 8 + b];
            if (run < K_TOP && run + h >= K_TOP) { s_B1 = tid * 8 + b; s_above = run; }
            run += h;
        }
    }
    __syncthreads();
    const int B1 = s_B1;

    for (int i = tid; i < scnt; i += 256) {
        unsigned uu = s_su[i];
        int key = (int)(uu >> 21);
        if (key > B1) {
            int p = atomicAdd(&s_cnt, 1);
            g_tv[r * K_TOP + p] = __uint_as_float(uu);
            g_ti[r * K_TOP + p] = s_si[i];
        } else if (key == B1) {
            int p = atomicAdd(&s_ccnt, 1);
            s_cu[p] = uu & 0x1FFFFFu; s_ci[p] = s_si[i];
        }
    }
    __syncthreads();

    int krem = K_TOP - s_above;
    int ccnt = s_ccnt;

    if (ccnt <= krem) {
        for (int i = tid; i < ccnt; i += 256) {
            int p = atomicAdd(&s_cnt, 1);
            g_tv[r * K_TOP + p] = __uint_as_float(((unsigned)B1 << 21) | s_cu[i]);
            g_ti[r * K_TOP + p] = s_ci[i];
        }
        return;
    }

    unsigned prefix21 = 0;
#pragma unroll 1
    for (int shift = 14; shift >= 0; shift -= 7) {
        if (tid < 128) s_hist[tid] = 0;
        if (tid == 0) s_sel = 0;
        __syncthreads();
        unsigned pmask = (shift == 14) ? 0u : ((0x1FFFFFu << (shift + 7)) & 0x1FFFFFu);
        for (int i = tid; i < ccnt; i += 256) {
            unsigned cu = s_cu[i];
            if ((cu & pmask) == prefix21) atomicAdd(&s_hist[(cu >> shift) & 127], 1);
        }
        __syncthreads();
        if (tid < 128) s_scan[tid] = s_hist[tid];
        __syncthreads();
#pragma unroll 1
        for (int off = 1; off < 128; off <<= 1) {
            int add = (tid < 128 && tid + off < 128) ? s_scan[tid + off] : 0;
            __syncthreads();
            if (tid < 128) s_scan[tid] += add;
            __syncthreads();
        }
        if (tid < 128) {
            int nxt = (tid < 127) ? s_scan[tid + 1] : 0;
            if (s_scan[tid] >= krem && nxt < krem) s_sel = tid;
        }
        __syncthreads();
        int dsel = s_sel;
        int above2 = (dsel < 127) ? s_scan[dsel + 1] : 0;
        krem -= above2;
        prefix21 |= ((unsigned)dsel) << shift;
        __syncthreads();
    }
    const unsigned kth_low = prefix21;
    for (int i = tid; i < ccnt; i += 256) {
        if (s_cu[i] > kth_low) {
            int p = atomicAdd(&s_cnt, 1);
            g_tv[r * K_TOP + p] = __uint_as_float(((unsigned)B1 << 21) | s_cu[i]);
            g_ti[r * K_TOP + p] = s_ci[i];
        }
    }
    __syncthreads();
    for (int i = tid; i < ccnt; i += 256) {
        if (s_cu[i] == kth_low) {
            int p = atomicAdd(&s_cnt, 1);
            if (p < K_TOP) {
                g_tv[r * K_TOP + p] = __uint_as_float(((unsigned)B1 << 21) | s_cu[i]);
                g_ti[r * K_TOP + p] = s_ci[i];
            }
        }
    }
}

// ---------------------------------------------------------------------------
// Top-32 fallback kernel: recompute row in fp32 and select exactly.
// Early-exits for rows the fast kernel handled (normal case: all of them).
// Register pressure is quarantined here.
// ---------------------------------------------------------------------------
__global__ __launch_bounds__(256)
void topk_fallback_kernel(const float* __restrict__ x, const float* __restrict__ Wenc,
                          const float* __restrict__ benc, const float* __restrict__ bdec) {
    const int r = blockIdx.x;
    const int scnt_raw = g_scnt[r];
    if (scnt_raw >= K_TOP && scnt_raw <= SCAP_G) return;   // fast path handled it

    __shared__ int s_hist[HBINS];
    __shared__ int s_warp[8];
    __shared__ int s_scan[128];
    __shared__ unsigned s_cu[CAP];
    __shared__ int s_ci[CAP];
    __shared__ float s_x[D_SZ];
    __shared__ int s_B1, s_above, s_cnt, s_ccnt, s_sel;

    const int tid = threadIdx.x;

#pragma unroll
    for (int i = tid; i < HBINS; i += 256) s_hist[i] = 0;
    if (tid == 0) { s_B1 = -1; s_above = 0; s_cnt = 0; s_ccnt = 0; }
    s_x[tid] = x[(size_t)r * D_SZ + tid] - bdec[tid];
    __syncthreads();

    unsigned u[32];
#pragma unroll 1
    for (int j = 0; j < 32; j++) {
        int h = tid * 32 + j;
        const float4* w4 = (const float4*)(Wenc + (size_t)h * D_SZ);
        float acc = benc[h];
#pragma unroll
        for (int dq = 0; dq < 64; dq++) {
            float4 wv = w4[dq];
            acc += s_x[dq * 4 + 0] * wv.x + s_x[dq * 4 + 1] * wv.y
                 + s_x[dq * 4 + 2] * wv.z + s_x[dq * 4 + 3] * wv.w;
        }
        u[j] = __float_as_uint(fmaxf(acc, 0.0f));
    }

#pragma unroll
    for (int j = 0; j < 32; j++)
        if (u[j]) atomicAdd(&s_hist[u[j] >> 21], 1);
    __syncthreads();

    int local, suf, total;
    suffix2048(s_hist, s_warp, tid, local, suf, total);
    {
        int run = suf - local;
#pragma unroll
        for (int b = 7; b >= 0; b--) {
            int h = s_hist[tid * 8 + b];
            if (run < K_TOP && run + h >= K_TOP) { s_B1 = tid * 8 + b; s_above = run; }
            run += h;
        }
    }
    __syncthreads();

    if (total < K_TOP) {
#pragma unroll
        for (int j = 0; j < 32; j++) {
            if (u[j]) {
                int p = atomicAdd(&s_cnt, 1);
                g_tv[r * K_TOP + p] = __uint_as_float(u[j]);
                g_ti[r * K_TOP + p] = tid * 32 + j;
            }
        }
        return;
    }

    const int B1 = s_B1;
#pragma unroll
    for (int j = 0; j < 32; j++) {
        unsigned uu = u[j];
        if (!uu) continue;
        int key = (int)(uu >> 21);
        int idx = tid * 32 + j;
        if (key > B1) {
            int p = atomicAdd(&s_cnt, 1);
            g_tv[r * K_TOP + p] = __uint_as_float(uu);
            g_ti[r * K_TOP + p] = idx;
        } else if (key == B1) {
            int p = atomicAdd(&s_ccnt, 1);
            if (p < CAP) { s_cu[p] = uu & 0x1FFFFFu; s_ci[p] = idx; }
        }
    }
    __syncthreads();

    int krem = K_TOP - s_above;
    int ccnt = s_ccnt < CAP ? s_ccnt : CAP;

    if (ccnt <= krem) {
        for (int i = tid; i < ccnt; i += 256) {
            int p = atomicAdd(&s_cnt, 1);
            g_tv[r * K_TOP + p] = __uint_as_float(((unsigned)B1 << 21) | s_cu[i]);
            g_ti[r * K_TOP + p] = s_ci[i];
        }
        return;
    }

    unsigned prefix21 = 0;
#pragma unroll 1
    for (int shift = 14; shift >= 0; shift -= 7) {
        if (tid < 128) s_hist[tid] = 0;
        if (tid == 0) s_sel = 0;
        __syncthreads();
        unsigned pmask = (shift == 14) ? 0u : ((0x1FFFFFu << (shift + 7)) & 0x1FFFFFu);
        for (int i = tid; i < ccnt; i += 256) {
            unsigned cu = s_cu[i];
            if ((cu & pmask) == prefix21) atomicAdd(&s_hist[(cu >> shift) & 127], 1);
        }
        __syncthreads();
        if (tid < 128) s_scan[tid] = s_hist[tid];
        __syncthreads();
#pragma unroll 1
        for (int off = 1; off < 128; off <<= 1) {
            int add = (tid < 128 && tid + off < 128) ? s_scan[tid + off] : 0;
            __syncthreads();
            if (tid < 128) s_scan[tid] += add;
            __syncthreads();
        }
        if (tid < 128) {
            int nxt = (tid < 127) ? s_scan[tid + 1] : 0;
            if (s_scan[tid] >= krem && nxt < krem) s_sel = tid;
        }
        __syncthreads();
        int dsel = s_sel;
        int above2 = (dsel < 127) ? s_scan[dsel + 1] : 0;
        krem -= above2;
        prefix21 |= ((unsigned)dsel) << shift;
        __syncthreads();
    }
    const unsigned kth_low = prefix21;

    for (int i = tid; i < ccnt; i += 256) {
        if (s_cu[i] > kth_low) {
            int p = atomicAdd(&s_cnt, 1);
            g_tv[r * K_TOP + p] = __uint_as_float(((unsigned)B1 << 21) | s_cu[i]);
            g_ti[r * K_TOP + p] = s_ci[i];
        }
    }
    __syncthreads();
    for (int i = tid; i < ccnt; i += 256) {
        if (s_cu[i] == kth_low) {
            int p = atomicAdd(&s_cnt, 1);
            if (p < K_TOP) {
                g_tv[r * K_TOP + p] = __uint_as_float(((unsigned)B1 << 21) | s_cu[i]);
                g_ti[r * K_TOP + p] = s_ci[i];
            }
        }
    }
}

// ---------------------------------------------------------------------------
// Sparse decode (unchanged)
// ---------------------------------------------------------------------------
__global__ __launch_bounds__(256)
void decode_kernel(const float* __restrict__ Wdec,
                   const float* __restrict__ b_dec,
                   float* __restrict__ out) {
    const int r = blockIdx.x;
    const int d = threadIdx.x;
    float acc = b_dec[d];
#pragma unroll
    for (int k = 0; k < K_TOP; k++) {
        float v  = g_tv[r * K_TOP + k];
        int   ix = g_ti[r * K_TOP + k];
        acc += v * __ldg(Wdec + (size_t)ix * D_SZ + d);
    }
    out[(size_t)r * D_SZ + d] = acc;
}

// ---------------------------------------------------------------------------
extern "C" void kernel_launch(void* const* d_in, const int* in_sizes, int n_in,
                              void* d_out, int out_size) {
    const float* x    = (const float*)d_in[0];
    const float* Wenc = (const float*)d_in[1];
    const float* benc = (const float*)d_in[2];
    const float* Wdec = (const float*)d_in[3];
    const float* bdec = (const float*)d_in[4];
    float* out = (float*)d_out;

    zero_cnt_kernel<<<B_SZ / 256, 256>>>();
    split_x_kernel<<<(B_SZ * D_SZ / 4) / 256, 256>>>(x, bdec);
    split_w_kernel<<<(H_SZ * D_SZ / 4) / 256, 256>>>(Wenc);

    static bool attr_set = false;
    if (!attr_set) {
        cudaFuncSetAttribute(enc_mma_kernel, cudaFuncAttributeMaxDynamicSharedMemorySize, SMEM_GEMM);
        attr_set = true;
    }
    dim3 grid(H_SZ / BN, B_SZ / BM);
    enc_mma_kernel<<<grid, 256, SMEM_GEMM>>>(benc);

    topk_fast_kernel<<<B_SZ, 256>>>();
    topk_fallback_kernel<<<B_SZ, 256>>>(x, Wenc, benc, bdec);

    decode_kernel<<<B_SZ, 256>>>(Wdec, bdec, out);
}